// round 1
// baseline (speedup 1.0000x reference)
#include <cuda_runtime.h>
#include <math.h>

#define H_DIM  1024
#define NHEADS 16
#define HEAD   64
#define BATCH  2
#define SEQ    2048
#define MROWS  (BATCH * SEQ)          // 4096
#define SCALE  0.03125f               // 1/sqrt(1024)

// Scratch for projected Q, K, V  ([B*T, H_DIM] row-major each)
__device__ float g_q[MROWS * H_DIM];
__device__ float g_k[MROWS * H_DIM];
__device__ float g_v[MROWS * H_DIM];

// ---------------------------------------------------------------------------
// Kernel 1: fused QKV projection.  out[m,n] = sum_k x[m,k]*W[n,k] + b[n]
// 64x64 block tile, 4x4 register tile per thread, BK=16. blockIdx.z picks Q/K/V.
// ---------------------------------------------------------------------------
__global__ __launch_bounds__(256) void qkv_gemm_kernel(
    const float* __restrict__ x,
    const float* __restrict__ Wq, const float* __restrict__ bq,
    const float* __restrict__ Wk, const float* __restrict__ bk,
    const float* __restrict__ Wv, const float* __restrict__ bv)
{
    const int which = blockIdx.z;
    const float* W    = (which == 0) ? Wq : (which == 1) ? Wk : Wv;
    const float* bias = (which == 0) ? bq : (which == 1) ? bk : bv;
    float*       out  = (which == 0) ? g_q : (which == 1) ? g_k : g_v;

    __shared__ float As[16][68];   // [k][m], padded
    __shared__ float Bs[16][68];   // [k][n], padded

    const int tid = threadIdx.x;           // 0..255
    const int tx  = tid & 15;              // n sub-tile
    const int ty  = tid >> 4;              // m sub-tile
    const int m0  = blockIdx.y * 64;
    const int n0  = blockIdx.x * 64;

    float acc[4][4] = {};

    const int lr = tid >> 2;               // 0..63 (row within tile)
    const int lc = (tid & 3) * 4;          // 0,4,8,12 (k offset)

    for (int k0 = 0; k0 < H_DIM; k0 += 16) {
        float4 a = *(const float4*)&x[(size_t)(m0 + lr) * H_DIM + k0 + lc];
        float4 b = *(const float4*)&W[(size_t)(n0 + lr) * H_DIM + k0 + lc];
        As[lc + 0][lr] = a.x; As[lc + 1][lr] = a.y;
        As[lc + 2][lr] = a.z; As[lc + 3][lr] = a.w;
        Bs[lc + 0][lr] = b.x; Bs[lc + 1][lr] = b.y;
        Bs[lc + 2][lr] = b.z; Bs[lc + 3][lr] = b.w;
        __syncthreads();

        #pragma unroll
        for (int kk = 0; kk < 16; kk++) {
            float ra[4], rb[4];
            #pragma unroll
            for (int i = 0; i < 4; i++) ra[i] = As[kk][ty * 4 + i];
            #pragma unroll
            for (int j = 0; j < 4; j++) rb[j] = Bs[kk][tx * 4 + j];
            #pragma unroll
            for (int i = 0; i < 4; i++)
                #pragma unroll
                for (int j = 0; j < 4; j++)
                    acc[i][j] += ra[i] * rb[j];
        }
        __syncthreads();
    }

    #pragma unroll
    for (int i = 0; i < 4; i++) {
        const int m = m0 + ty * 4 + i;
        #pragma unroll
        for (int j = 0; j < 4; j++) {
            const int n = n0 + tx * 4 + j;
            out[(size_t)m * H_DIM + n] = acc[i][j] + bias[n];
        }
    }
}

// ---------------------------------------------------------------------------
// Kernel 2: causal attention per (b, h, 64-row q tile).
// 64 threads: thread t owns query row qt*64+t. Online softmax, K/V tiles in smem.
// ---------------------------------------------------------------------------
__global__ __launch_bounds__(64) void attn_kernel(float* __restrict__ out)
{
    const int qt  = blockIdx.x;            // 0..31  (q tile)
    const int bh  = blockIdx.y;            // 0..31  (batch*head)
    const int tid = threadIdx.x;           // 0..63
    const int b   = bh >> 4;
    const int h   = bh & 15;

    const int qrow = qt * 64 + tid;
    const size_t base = ((size_t)(b * SEQ)) * H_DIM + h * HEAD;

    // q row in registers (16 x float4)
    float4 qv[16];
    {
        const float4* qp = (const float4*)&g_q[base + (size_t)qrow * H_DIM];
        #pragma unroll
        for (int i = 0; i < 16; i++) qv[i] = qp[i];
    }

    float4 o4[16];
    #pragma unroll
    for (int i = 0; i < 16; i++) o4[i] = make_float4(0.f, 0.f, 0.f, 0.f);
    float mmax = -1e30f, l = 0.f;

    __shared__ float4 Ks[64][17];          // padded rows (68 floats)
    __shared__ float4 Vs[64][17];

    for (int kt = 0; kt <= qt; kt++) {
        __syncthreads();
        const int krow = kt * 64 + tid;
        const float4* kp = (const float4*)&g_k[base + (size_t)krow * H_DIM];
        const float4* vp = (const float4*)&g_v[base + (size_t)krow * H_DIM];
        #pragma unroll
        for (int i = 0; i < 16; i++) {
            Ks[tid][i] = kp[i];
            Vs[tid][i] = vp[i];
        }
        __syncthreads();

        const int jmax = (kt == qt) ? tid : 63;
        for (int j = 0; j <= jmax; j++) {
            // s = q . K[j]
            float s0 = 0.f, s1 = 0.f, s2 = 0.f, s3 = 0.f;
            #pragma unroll
            for (int i = 0; i < 16; i++) {
                float4 kv = Ks[j][i];
                s0 += qv[i].x * kv.x;
                s1 += qv[i].y * kv.y;
                s2 += qv[i].z * kv.z;
                s3 += qv[i].w * kv.w;
            }
            float s = ((s0 + s1) + (s2 + s3)) * SCALE;

            if (s > mmax) {                  // rare after warmup
                float c = __expf(mmax - s);
                l *= c;
                #pragma unroll
                for (int i = 0; i < 16; i++) {
                    o4[i].x *= c; o4[i].y *= c; o4[i].z *= c; o4[i].w *= c;
                }
                mmax = s;
            }
            float p = __expf(s - mmax);
            l += p;
            #pragma unroll
            for (int i = 0; i < 16; i++) {
                float4 vv = Vs[j][i];
                o4[i].x += p * vv.x;
                o4[i].y += p * vv.y;
                o4[i].z += p * vv.z;
                o4[i].w += p * vv.w;
            }
        }
    }

    const float inv = 1.f / l;
    float4* op = (float4*)&out[base + (size_t)qrow * H_DIM];
    #pragma unroll
    for (int i = 0; i < 16; i++) {
        float4 r = o4[i];
        r.x *= inv; r.y *= inv; r.z *= inv; r.w *= inv;
        op[i] = r;
    }
}

// ---------------------------------------------------------------------------
extern "C" void kernel_launch(void* const* d_in, const int* in_sizes, int n_in,
                              void* d_out, int out_size)
{
    const float* x  = (const float*)d_in[0];
    const float* Wq = (const float*)d_in[1];
    const float* bq = (const float*)d_in[2];
    const float* Wk = (const float*)d_in[3];
    const float* bk = (const float*)d_in[4];
    const float* Wv = (const float*)d_in[5];
    const float* bv = (const float*)d_in[6];
    float* out = (float*)d_out;

    dim3 ggrid(H_DIM / 64, MROWS / 64, 3);   // (16, 64, 3)
    qkv_gemm_kernel<<<ggrid, 256>>>(x, Wq, bq, Wk, bk, Wv, bv);

    dim3 agrid(SEQ / 64, BATCH * NHEADS);    // (32, 32)
    attn_kernel<<<agrid, 64>>>(out);
}